// round 10
// baseline (speedup 1.0000x reference)
#include <cuda_runtime.h>
#include <cuda_fp16.h>
#include <cstdint>
#include <math.h>

// Problem constants (CTCLoss_70961449664599): T=2048, B=64, V=512, S=256
#define T_DIM 2048
#define B_DIM 64
#define V_DIM 512
#define S_DIM 256
#define L_DIM 513
#define BB    8                 // steps per publish block
#define RING  32                // boundary ring slots (= 4 publish blocks)
#define PF    8                 // G prefetch depth (= BB)
#define TPAD  (T_DIM + 2 * PF)  // padded time so prefetch never goes OOB
#define NEG2  (-1.0e30f)
#define LOG2E_F 1.4426950408889634f
#define LN2_F   0.6931471805599453f

// Scratch (__device__ globals per allocation-free rule).
// G2[b][t][p] = (log2-prob of symbol targets[b][p], log2-prob of blank), half2.
__device__ __align__(16) __half2 g_G2[(size_t)B_DIM * TPAD * S_DIM];  // ~138 MB
__device__ float g_partial[B_DIM];

__device__ __forceinline__ float ex2f_(float x) {
    float y; asm("ex2.approx.f32 %0, %1;" : "=f"(y) : "f"(x)); return y;
}
__device__ __forceinline__ float lg2f_(float x) {
    float y; asm("lg2.approx.f32 %0, %1;" : "=f"(y) : "f"(x)); return y;
}
__device__ __forceinline__ float lse2_(float a, float b) {   // 2-term logaddexp2
    const float m = fmaxf(a, b);
    return m + lg2f_(1.0f + ex2f_(-fabsf(a - b)));
}
__device__ __forceinline__ unsigned int smem_u32_(const void* p) {
    unsigned int a;
    asm("{ .reg .u64 t; cvta.to.shared.u64 t, %1; cvt.u32.u64 %0, t; }"
        : "=r"(a) : "l"(p));
    return a;
}
__device__ __forceinline__ void st_release_sh(int* p, int v) {
    asm volatile("st.release.cta.shared.u32 [%0], %1;"
                 :: "r"(smem_u32_(p)), "r"(v) : "memory");
}
__device__ __forceinline__ int ld_acquire_sh(const int* p) {
    int v;
    asm volatile("ld.acquire.cta.shared.u32 %0, [%1];"
                 : "=r"(v) : "r"(smem_u32_(p)) : "memory");
    return v;
}
// bounded spin: wait until *p >= want (release/acquire ordered)
__device__ __forceinline__ void spin_ge_(const int* p, int want) {
    int guard = 1 << 24;
    while (ld_acquire_sh(p) < want && --guard) { __nanosleep(32); }
}

// ---------------------------------------------------------------------------
// Phase 1: log-softmax (log2 domain) + gather into half2 pairs.
// Grid: (B, T/8), block: 256 threads (8 warps, 1 warp per t-row)
// ---------------------------------------------------------------------------
__global__ __launch_bounds__(256) void ctc_phase1(
    const float* __restrict__ x, const int* __restrict__ targets)
{
    __shared__ float sh_row[8][V_DIM];
    __shared__ int   sh_tgt[S_DIM];

    const int b    = blockIdx.x;
    const int tid  = threadIdx.x;
    const int w    = tid >> 5;
    const int lane = tid & 31;

    sh_tgt[tid] = targets[b * S_DIM + tid];
    __syncthreads();

    const int t = blockIdx.y * 8 + w;
    const float4* row = (const float4*)(x + ((size_t)t * B_DIM + b) * V_DIM);

    float s = 0.0f;
    float4* shv = (float4*)sh_row[w];
#pragma unroll
    for (int k = 0; k < 4; k++) {
        float4 v = row[lane + 32 * k];
        shv[lane + 32 * k] = v;
        s += ex2f_(v.x * LOG2E_F) + ex2f_(v.y * LOG2E_F)
           + ex2f_(v.z * LOG2E_F) + ex2f_(v.w * LOG2E_F);
    }
#pragma unroll
    for (int o = 16; o; o >>= 1) s += __shfl_xor_sync(0xffffffffu, s, o);
    const float lse2v = lg2f_(s);
    const float blankv = sh_row[w][0] * LOG2E_F - lse2v;

    __half2* gout = g_G2 + ((size_t)b * TPAD + t) * S_DIM;
#pragma unroll
    for (int j = lane; j < 256; j += 32) {
        const float symv = sh_row[w][sh_tgt[j]] * LOG2E_F - lse2v;
        gout[j] = __floats2half2_rn(symv, blankv);   // .x = symbol, .y = blank
    }
}

// ---------------------------------------------------------------------------
// Phase 2: barrier-free skewed wavefront.
// Warps 0..7: thread p = tid owns pair (2p, 2p+1), alpha in registers.
//   - alpha(2p-1) via shfl_up; lane 0 via per-boundary SMEM ring.
//   - warp w publishes lane-31 odd alpha into ring[w], tag every BB steps.
// Warp 8: lane-uniform, owns position 512 (blank), consumes ring[7].
// ---------------------------------------------------------------------------
#define NTH2 288
__global__ __launch_bounds__(NTH2) void ctc_phase2(
    const int* __restrict__ targets,
    const int* __restrict__ in_len,
    const int* __restrict__ tgt_len)
{
    __shared__ float ring[8][RING];
    __shared__ int   ptag[8], ctag[8];
    __shared__ float sh_alpha[L_DIM];

    const int b    = blockIdx.x;
    const int tid  = threadIdx.x;
    const int w    = tid >> 5;
    const int lane = tid & 31;
    const int Lin  = in_len[b];           // block-uniform
    const int Lt   = tgt_len[b];
    const bool mainw = (w < 8);
    const int p    = mainw ? tid : 255;   // pair index (warp 8 reuses col 255 for blank)

    if (tid < 8) { ptag[tid] = 0; ctag[tid] = 0; }

    bool allow2 = false;
    if (mainw) {
        const int curt  = targets[b * S_DIM + p];
        const int prevt = (p > 0) ? targets[b * S_DIM + p - 1] : 0;
        allow2 = (curt != prevt);
    }

    const __half2* gptr = g_G2 + (size_t)b * TPAD * S_DIM + p;

    // t = 0 init
    float a_e, a_o, a_x = NEG2;
    {
        const __half2 g0 = __ldg(gptr);
        a_e = (mainw && p == 0) ? __high2float(g0) : NEG2;   // pos 0 (blank)
        a_o = (mainw && p == 0) ? __low2float(g0)  : NEG2;   // pos 1 (symbol)
    }
    if (mainw && lane == 31) ring[w][0] = a_o;   // boundary alpha(0)
    __syncthreads();                             // tags + slot 0 visible

    // G prefetch for t = 1..PF
    float gsym[PF], gbl[PF];
#pragma unroll
    for (int k = 0; k < PF; k++) {
        const __half2 v = __ldg(gptr + (size_t)(1 + k) * S_DIM);
        gsym[k] = __low2float(v); gbl[k] = __high2float(v);
    }

    const int nsteps = Lin - 1;
    const int nblk   = (nsteps + BB - 1) / BB;

    if (mainw) {
        for (int n = 0; n < nblk; n++) {
            if (n >= 3) spin_ge_(&ctag[w], n - 2);        // slot-reuse backpressure
            if (w > 0)  spin_ge_(&ptag[w - 1], n + 1);    // producer published block n
            const int t0   = 1 + n * BB;
            const int kmax = (nsteps - n * BB < BB) ? (nsteps - n * BB) : BB;
#pragma unroll
            for (int k = 0; k < BB; k++) {
                if (k >= kmax) break;
                const int t = t0 + k;
                float aleft = __shfl_up_sync(0xffffffffu, a_o, 1);
                if (lane == 0)
                    aleft = (w > 0) ? ring[w - 1][(t - 1) & (RING - 1)] : NEG2;
                // even (blank) position 2p: 2-term
                const float ne = lse2_(a_e, aleft) + gbl[k];
                // odd (symbol) position 2p+1: 3-term
                const float am2 = allow2 ? aleft : NEG2;
                const float m  = fmaxf(a_o, fmaxf(a_e, am2));
                const float sm = ex2f_(a_o - m) + ex2f_(a_e - m) + ex2f_(am2 - m);
                const float no = m + lg2f_(sm) + gsym[k];
                a_e = ne; a_o = no;
                if (lane == 31) ring[w][t & (RING - 1)] = no;
                // prefetch t + PF
                const __half2 v = __ldg(gptr + (size_t)(t + PF) * S_DIM);
                gsym[k] = __low2float(v); gbl[k] = __high2float(v);
            }
            if (lane == 31) st_release_sh(&ptag[w], n + 1);
            if (w > 0 && lane == 0) st_release_sh(&ctag[w - 1], n + 1);
        }
    } else {
        // warp 8: position 512 (blank). Lane-uniform compute (broadcast reads).
        for (int n = 0; n < nblk; n++) {
            spin_ge_(&ptag[7], n + 1);
            const int t0   = 1 + n * BB;
            const int kmax = (nsteps - n * BB < BB) ? (nsteps - n * BB) : BB;
#pragma unroll
            for (int k = 0; k < BB; k++) {
                if (k >= kmax) break;
                const int t = t0 + k;
                const float aleft = ring[7][(t - 1) & (RING - 1)];  // alpha(t-1,511)
                a_x = lse2_(a_x, aleft) + gbl[k];
                const __half2 v = __ldg(gptr + (size_t)(t + PF) * S_DIM);
                gsym[k] = __low2float(v); gbl[k] = __high2float(v);
            }
            if (lane == 0) st_release_sh(&ctag[7], n + 1);
        }
    }

    if (mainw) { sh_alpha[2 * p] = a_e; sh_alpha[2 * p + 1] = a_o; }
    if (tid == 256) sh_alpha[512] = a_x;
    __syncthreads();

    if (tid == 0) {
        const int idx = 2 * Lt;
        const float la2 = lse2_(sh_alpha[idx], sh_alpha[idx - 1]);
        float loss = -la2 * LN2_F;
        if (!isfinite(loss) || loss > 0.5e30f) loss = 0.0f;   // zero_infinity
        g_partial[b] = loss / (float)Lt;
    }
}

// ---------------------------------------------------------------------------
// Phase 3: mean over batch -> out[0]
// ---------------------------------------------------------------------------
__global__ void ctc_phase3(float* __restrict__ out)
{
    const int lane = threadIdx.x;
    float v = g_partial[lane] + g_partial[lane + 32];
#pragma unroll
    for (int o = 16; o; o >>= 1) v += __shfl_xor_sync(0xffffffffu, v, o);
    if (lane == 0) out[0] = v / (float)B_DIM;
}

// ---------------------------------------------------------------------------
extern "C" void kernel_launch(void* const* d_in, const int* in_sizes, int n_in,
                              void* d_out, int out_size)
{
    const float* x    = (const float*)d_in[0];   // (T, B, V) float32
    const int*   tgt  = (const int*)d_in[1];     // (B, S) int32
    const int*   ilen = (const int*)d_in[2];     // (B,) int32
    const int*   tlen = (const int*)d_in[3];     // (B,) int32
    float*       out  = (float*)d_out;

    dim3 g1(B_DIM, T_DIM / 8);
    ctc_phase1<<<g1, 256>>>(x, tgt);
    ctc_phase2<<<B_DIM, NTH2>>>(tgt, ilen, tlen);
    ctc_phase3<<<1, 32>>>(out);
}

// round 12
// speedup vs baseline: 2.1379x; 2.1379x over previous
#include <cuda_runtime.h>
#include <cuda_fp16.h>
#include <cstdint>
#include <math.h>

// Problem constants (CTCLoss_70961449664599): T=2048, B=64, V=512, S=256
#define T_DIM 2048
#define B_DIM 64
#define V_DIM 512
#define S_DIM 256
#define CH    16                 // time steps staged per cp.async chunk
#define TPAD  (T_DIM + 2 * CH)   // padded time rows
#define NEG2  (-1.0e30f)
#define LOG2E_F 1.4426950408889634f
#define LN2_F   0.6931471805599453f

// Scratch (allocation-free rule: __device__ globals).
// G2[b][t][p] = half2( log2 p(symbol targets[b][p]), log2 p(blank) )
__device__ __align__(16) __half2 g_G2[(size_t)B_DIM * TPAD * S_DIM];
__device__ float g_partial[B_DIM];

__device__ __forceinline__ float ex2f_(float x) {
    float y; asm("ex2.approx.f32 %0, %1;" : "=f"(y) : "f"(x)); return y;
}
__device__ __forceinline__ float lg2f_(float x) {
    float y; asm("lg2.approx.f32 %0, %1;" : "=f"(y) : "f"(x)); return y;
}
__device__ __forceinline__ float lse2_(float a, float b) {   // 2 MUFU
    const float m = fmaxf(a, b);
    return m + lg2f_(1.0f + ex2f_(-fabsf(a - b)));
}
__device__ __forceinline__ float lse3_(float a, float b, float c) {  // 4 MUFU
    const float m = fmaxf(a, fmaxf(b, c));
    return m + lg2f_(ex2f_(a - m) + ex2f_(b - m) + ex2f_(c - m));
}
__device__ __forceinline__ unsigned int smem_u32(const void* p) {
    unsigned int a;
    asm("{ .reg .u64 t; cvta.to.shared.u64 t, %1; cvt.u32.u64 %0, t; }"
        : "=r"(a) : "l"(p));
    return a;
}

// ---------------------------------------------------------------------------
// Phase 1: log-softmax (log2 domain) + gather into half2 (symbol, blank).
// Grid: (B, T/8), block: 256 threads (8 warps, 1 warp per t-row)
// ---------------------------------------------------------------------------
__global__ __launch_bounds__(256) void ctc_phase1(
    const float* __restrict__ x, const int* __restrict__ targets)
{
    __shared__ float sh_row[8][V_DIM];
    __shared__ int   sh_tgt[S_DIM];

    const int b    = blockIdx.x;
    const int tid  = threadIdx.x;
    const int w    = tid >> 5;
    const int lane = tid & 31;

    sh_tgt[tid] = targets[b * S_DIM + tid];
    __syncthreads();

    const int t = blockIdx.y * 8 + w;
    const float4* row = (const float4*)(x + ((size_t)t * B_DIM + b) * V_DIM);

    float s = 0.0f;
    float4* shv = (float4*)sh_row[w];
#pragma unroll
    for (int k = 0; k < 4; k++) {
        float4 v = row[lane + 32 * k];
        shv[lane + 32 * k] = v;
        s += ex2f_(v.x * LOG2E_F) + ex2f_(v.y * LOG2E_F)
           + ex2f_(v.z * LOG2E_F) + ex2f_(v.w * LOG2E_F);
    }
#pragma unroll
    for (int o = 16; o; o >>= 1) s += __shfl_xor_sync(0xffffffffu, s, o);
    const float lse2v = lg2f_(s);
    const float blankv = sh_row[w][0] * LOG2E_F - lse2v;

    __half2* gout = g_G2 + ((size_t)b * TPAD + t) * S_DIM;
#pragma unroll
    for (int j = lane; j < 256; j += 32) {
        const float symv = sh_row[w][sh_tgt[j]] * LOG2E_F - lse2v;
        gout[j] = __floats2half2_rn(symv, blankv);   // .x = symbol, .y = blank
    }
}

// ---------------------------------------------------------------------------
// Phase 2: alpha recursion (log2 domain), K=2 halo blocking.
// 288 threads: thread p<256 owns pair (2p, 2p+1); thread 256 owns pos 512;
// threads 257..287 idle. Per barrier: 2 time steps; each thread redundantly
// computes step-1 of pair p-1 (halo) so step-2 of pair p needs no sync.
// alpha in SMEM double buffer abuf (indices shifted +4, pads = NEG2).
// G staged CH rows/chunk via cp.async double buffer.
// ---------------------------------------------------------------------------
#define NTH 288
__global__ __launch_bounds__(NTH) void ctc_phase2(
    const int* __restrict__ targets,
    const int* __restrict__ in_len,
    const int* __restrict__ tgt_len)
{
    __shared__ __align__(16) __half2 sg[2][CH * 256];   // 2 x 16 KB
    __shared__ float abuf[2][517];                      // [0..3] = NEG2 pads

    const int b   = blockIdx.x;
    const int tid = threadIdx.x;
    const int Lin = in_len[b];            // block-uniform
    const int Lt  = tgt_len[b];

    const bool mainp = (tid < 256);
    const bool t512  = (tid == 256);
    const int  p     = mainp ? tid : 255;       // load column (t512 uses 255)
    const int  pm1   = (p > 0) ? p - 1 : 0;

    // allow2 flags: pair p and halo pair p-1 (symbols >= 1, so only repeat check)
    const int tg0 = targets[b * S_DIM + p];
    const int tgm = (p > 0) ? targets[b * S_DIM + p - 1] : 0;
    const int tgm2 = (p > 1) ? targets[b * S_DIM + p - 2] : 0;
    const bool al2  = t512 ? (targets[b*S_DIM+255] != targets[b*S_DIM+254])
                           : (tg0 != tgm);      // pair p (or pair 255 for t512)
    const bool al2m = (tgm != tgm2);            // halo pair p-1 (p>=1)

    const __half2* gb2 = g_G2 + (size_t)b * TPAD * S_DIM;

    // t = 0 init: only positions 0 (blank) and 1 (symbol 0) live.
    if (tid < 4) { abuf[0][tid] = NEG2; abuf[1][tid] = NEG2; }
    if (mainp) {
        if (tid == 0) {
            const __half2 g0 = __ldg(gb2);
            abuf[0][4] = __high2float(g0);   // pos 0 = blank
            abuf[0][5] = __low2float(g0);    // pos 1 = symbol 0
        } else {
            abuf[0][4 + 2 * tid] = NEG2;
            abuf[0][5 + 2 * tid] = NEG2;
        }
    } else if (t512) {
        abuf[0][516] = NEG2;
    }

    const unsigned int sd0 = smem_u32(&sg[0][0]);
    const unsigned int sd1 = smem_u32(&sg[1][0]);

    // stage chunk c = G2 rows [1 + c*CH, 1 + c*CH + CH) -> sg[c&1]
    auto stage = [&](int c) {
        const char* src = (const char*)(gb2 + (size_t)(1 + c * CH) * 256);
        const unsigned int dst = (c & 1) ? sd1 : sd0;
        if (tid < 256) {
#pragma unroll
            for (int k = 0; k < 4; k++) {     // 256 threads x 4 x 16B = 16 KB
                const int e = tid + k * 256;
                asm volatile("cp.async.cg.shared.global [%0], [%1], 16;"
                             :: "r"(dst + e * 16), "l"(src + (size_t)e * 16));
            }
        }
        asm volatile("cp.async.commit_group;");
    };

    stage(0);
    const int nsteps = Lin - 1;
    const int nch = (nsteps + CH - 1) / CH;

    int cur = 0;
    for (int c = 0; c < nch; c++) {
        stage(c + 1);
        asm volatile("cp.async.wait_group 1;");
        __syncthreads();                        // chunk c visible; abuf settled

        const __half2* sb = sg[c & 1];
        const int tmax = min(CH, nsteps - c * CH);   // block-uniform
        for (int k = 0; k < tmax; ) {
            const bool two = (k + 1 < tmax);         // block-uniform
            const float* A = abuf[cur];
            float nv_e, nv_o;                        // values to write

            if (mainp) {
                // old alphas: positions 2p-3 .. 2p+1  (abuf idx 2p+1 .. 2p+5)
                const float o_m3 = A[2 * p + 1];
                const float o_m2 = A[2 * p + 2];
                const float o_m1 = A[2 * p + 3];
                const float o_e  = A[2 * p + 4];
                const float o_o  = A[2 * p + 5];
                const __half2 h  = sb[k * 256 + p];
                const __half2 hm = sb[k * 256 + pm1];
                const float gs  = __low2float(h);
                const float gbl = __high2float(h);
                const float gsm = __low2float(hm);

                // step 1
                const float n1_m2 = (p > 0) ? lse2_(o_m2, o_m3) + gbl : NEG2;
                const float n1_m1 = (p > 0)
                    ? lse3_(o_m1, o_m2, al2m ? o_m3 : NEG2) + gsm : NEG2;
                const float n1_e  = lse2_(o_e, o_m1) + gbl;
                const float n1_o  = lse3_(o_o, o_e, al2 ? o_m1 : NEG2) + gs;
                (void)n1_m2;

                if (two) {
                    const __half2 h2 = sb[(k + 1) * 256 + p];
                    const float gs2  = __low2float(h2);
                    const float gbl2 = __high2float(h2);
                    nv_e = lse2_(n1_e, n1_m1) + gbl2;
                    nv_o = lse3_(n1_o, n1_e, al2 ? n1_m1 : NEG2) + gs2;
                } else {
                    nv_e = n1_e; nv_o = n1_o;
                }
            } else if (t512) {
                // position 512 (blank); needs old 509..512 (abuf idx 513..516)
                const float o509 = A[513];
                const float o510 = A[514];
                const float o511 = A[515];
                const float o512 = A[516];
                const __half2 h  = sb[k * 256 + 255];
                const float gs  = __low2float(h);     // symbol 255 (for 511)
                const float gbl = __high2float(h);

                const float n1_511 = lse3_(o511, o510, al2 ? o509 : NEG2) + gs;
                const float n1_512 = lse2_(o512, o511) + gbl;
                if (two) {
                    const float gbl2 = __high2float(sb[(k + 1) * 256 + 255]);
                    nv_e = lse2_(n1_512, n1_511) + gbl2;
                } else {
                    nv_e = n1_512;
                }
                nv_o = 0.0f;
            } else {
                nv_e = 0.0f; nv_o = 0.0f;
            }

            // write
            if (mainp) {
                abuf[cur ^ 1][4 + 2 * p] = nv_e;
                abuf[cur ^ 1][5 + 2 * p] = nv_o;
            } else if (t512) {
                abuf[cur ^ 1][516] = nv_e;
            }
            __syncthreads();
            cur ^= 1;
            k += two ? 2 : 1;
        }
    }

    if (tid == 0) {
        const float* A = abuf[cur];
        const int idx = 2 * Lt;
        const float la2 = lse2_(A[4 + idx], A[3 + idx]);
        float loss = -la2 * LN2_F;
        if (!isfinite(loss) || loss > 0.5e30f) loss = 0.0f;   // zero_infinity
        g_partial[b] = loss / (float)Lt;
    }
}

// ---------------------------------------------------------------------------
// Phase 3: mean over batch -> out[0]
// ---------------------------------------------------------------------------
__global__ void ctc_phase3(float* __restrict__ out)
{
    const int lane = threadIdx.x;
    float v = g_partial[lane] + g_partial[lane + 32];
#pragma unroll
    for (int o = 16; o; o >>= 1) v += __shfl_xor_sync(0xffffffffu, v, o);
    if (lane == 0) out[0] = v / (float)B_DIM;
}

// ---------------------------------------------------------------------------
extern "C" void kernel_launch(void* const* d_in, const int* in_sizes, int n_in,
                              void* d_out, int out_size)
{
    const float* x    = (const float*)d_in[0];   // (T, B, V) float32
    const int*   tgt  = (const int*)d_in[1];     // (B, S) int32
    const int*   ilen = (const int*)d_in[2];     // (B,) int32
    const int*   tlen = (const int*)d_in[3];     // (B,) int32
    float*       out  = (float*)d_out;

    dim3 g1(B_DIM, T_DIM / 8);
    ctc_phase1<<<g1, 256>>>(x, tgt);
    ctc_phase2<<<B_DIM, NTH>>>(tgt, ilen, tlen);
    ctc_phase3<<<1, 32>>>(out);
}

// round 13
// speedup vs baseline: 2.5845x; 1.2089x over previous
#include <cuda_runtime.h>
#include <cuda_fp16.h>
#include <cstdint>
#include <math.h>

// Problem constants (CTCLoss_70961449664599): T=2048, B=64, V=512, S=256
#define T_DIM 2048
#define B_DIM 64
#define V_DIM 512
#define S_DIM 256
#define L_DIM (2 * S_DIM + 1)   // 513 extended positions
#define GP2   272               // padded row of halfs: cols 0..255 symbols, 256 blank
#define CHUNK 32                // time steps staged per cp.async group
#define TPAD  (T_DIM + 2 * CHUNK)
#define NEG2  (-1.0e30f)
#define LOG2E_F 1.4426950408889634f
#define LN2_F   0.6931471805599453f

// Scratch (allocation-free rule: __device__ globals). Layout: G[b][t][j].
__device__ __align__(16) __half g_G[(size_t)B_DIM * TPAD * GP2];
__device__ float g_partial[B_DIM];

__device__ __forceinline__ float ex2f_(float x) {
    float y; asm("ex2.approx.f32 %0, %1;" : "=f"(y) : "f"(x)); return y;
}
__device__ __forceinline__ float lg2f_(float x) {
    float y; asm("lg2.approx.f32 %0, %1;" : "=f"(y) : "f"(x)); return y;
}
__device__ __forceinline__ __half2 h2ex2_(__half2 x) {   // 1 MUFU, two exp2s
    unsigned int xi = *reinterpret_cast<unsigned int*>(&x), yi;
    asm("ex2.approx.f16x2 %0, %1;" : "=r"(yi) : "r"(xi));
    return *reinterpret_cast<__half2*>(&yi);
}
__device__ __forceinline__ float lse2_(float a, float b) {   // 2 MUFU
    const float m = fmaxf(a, b);
    return m + lg2f_(1.0f + ex2f_(-fabsf(a - b)));
}
__device__ __forceinline__ unsigned int smem_u32(const void* p) {
    unsigned int a;
    asm("{ .reg .u64 t; cvta.to.shared.u64 t, %1; cvt.u32.u64 %0, t; }"
        : "=r"(a) : "l"(p));
    return a;
}

// ---------------------------------------------------------------------------
// Phase 1: per (t,b) row -> log2-sum-exp; gathered log2-probs (fp16)
//   G[b][t][j] : j<256 -> symbol targets[b][j] (ext pos 2j+1), j=256 -> blank
// Grid: (B, T/8), block: 256 threads (8 warps, 1 warp per t-row)
// ---------------------------------------------------------------------------
__global__ __launch_bounds__(256) void ctc_phase1(
    const float* __restrict__ x, const int* __restrict__ targets)
{
    __shared__ float sh_row[8][V_DIM];
    __shared__ int   sh_tgt[S_DIM];

    const int b    = blockIdx.x;
    const int tid  = threadIdx.x;
    const int w    = tid >> 5;
    const int lane = tid & 31;

    sh_tgt[tid] = targets[b * S_DIM + tid];
    __syncthreads();

    const int t = blockIdx.y * 8 + w;
    const float4* row = (const float4*)(x + ((size_t)t * B_DIM + b) * V_DIM);

    float s = 0.0f;
    float4* shv = (float4*)sh_row[w];
#pragma unroll
    for (int k = 0; k < 4; k++) {
        float4 v = row[lane + 32 * k];
        shv[lane + 32 * k] = v;
        s += ex2f_(v.x * LOG2E_F) + ex2f_(v.y * LOG2E_F)
           + ex2f_(v.z * LOG2E_F) + ex2f_(v.w * LOG2E_F);
    }
#pragma unroll
    for (int o = 16; o; o >>= 1) s += __shfl_xor_sync(0xffffffffu, s, o);
    const float lse2v = lg2f_(s);

    __half* gout = g_G + ((size_t)b * TPAD + t) * GP2;
#pragma unroll
    for (int j = lane; j < 257; j += 32) {
        const int sym = (j < 256) ? sh_tgt[j] : 0;
        gout[j] = __float2half_rn(sh_row[w][sym] * LOG2E_F - lse2v);
    }
}

// ---------------------------------------------------------------------------
// Phase 2: alpha recursion (log2 domain), parity-segregated warps:
//   tid   0..256  -> even positions l = 2*tid   (blanks,  2-MUFU LSE2)
//   tid 257..287  -> idle (warp alignment)
//   tid 288..543  -> odd positions  l = 2*i+1   (symbols, 2-MUFU LSE3)
// Own alpha kept in register (saves one LDS per step). G staged CHUNK steps
// at a time into double-buffered SMEM via cp.async. One __syncthreads/step.
// ---------------------------------------------------------------------------
#define NTH 544

__global__ __launch_bounds__(NTH) void ctc_phase2(
    const int* __restrict__ targets,
    const int* __restrict__ in_len,
    const int* __restrict__ tgt_len)
{
    __shared__ __align__(16) __half sgbuf[2][CHUNK * GP2];  // 34816 B
    __shared__ float abuf[2][L_DIM + 2];                    // [0],[1] NEG2 pads

    const int b   = blockIdx.x;
    const int tid = threadIdx.x;
    const int Lin = in_len[b];             // block-uniform
    const int Lt  = tgt_len[b];

    const bool is_even = (tid < 257);
    const bool act     = is_even | (tid >= 288);
    const int  i       = tid - 288;                      // odd pair index
    const int  l       = is_even ? (2 * tid) : (2 * i + 1);
    const int  j       = is_even ? 256 : i;              // column within a row

    bool allow2 = false;
    if (!is_even && act) {
        const int curt  = targets[b * S_DIM + i];
        const int prevt = (i > 0) ? targets[b * S_DIM + i - 1] : 0;
        allow2 = (curt != prevt);          // symbols >= 1, repeat check only
    }

    const __half* gbase = g_G + (size_t)b * TPAD * GP2;

    // t = 0 init: only positions 0,1 live
    if (tid < 2) { abuf[0][tid] = NEG2; abuf[1][tid] = NEG2; }
    float a_own = NEG2;
    if (act) {
        a_own = (l < 2) ? __half2float(__ldg(gbase + j)) : NEG2;
        abuf[0][2 + l] = a_own;
    }

    const unsigned int sdst0 = smem_u32(&sgbuf[0][0]);
    const unsigned int sdst1 = smem_u32(&sgbuf[1][0]);

    // stage chunk c (rows 1 + c*CHUNK .. +CHUNK-1) into sgbuf[c&1]
    auto stage = [&](int c) {
        const char* src = (const char*)(gbase + (size_t)(1 + c * CHUNK) * GP2);
        const unsigned int dst = (c & 1) ? sdst1 : sdst0;
#pragma unroll
        for (int k = 0; k < 2; k++) {
            const int e = tid + k * NTH;   // 2*544 = 1088 uint4 = whole chunk
            asm volatile("cp.async.cg.shared.global [%0], [%1], 16;"
                         :: "r"(dst + e * 16), "l"(src + (size_t)e * 16));
        }
        asm volatile("cp.async.commit_group;");
    };

    stage(0);
    const int nch = (Lin - 1 + CHUNK - 1) / CHUNK;

    int cur = 0;
    for (int c = 0; c < nch; c++) {
        stage(c + 1);                            // overlap with this chunk
        asm volatile("cp.async.wait_group 1;");  // chunk c resident
        __syncthreads();

        const __half* sb = sgbuf[c & 1];
        const int tmax = min(CHUNK, Lin - 1 - c * CHUNK);   // block-uniform
        for (int k = 0; k < tmax; k++) {
            if (act) {
                const float g = __half2float(sb[k * GP2 + j]);
                const float* A = abuf[cur];
                float v;
                if (is_even) {
                    v = lse2_(a_own, A[1 + l]) + g;          // blank: 2-term
                } else {
                    // symbol: 3-term LSE, 2 MUFU total.
                    // One delta is exactly 0; compute ex2 of 2nd/3rd deltas
                    // in a single f16x2 MUFU op.
                    const float a0  = a_own;
                    const float a1  = A[1 + l];
                    const float a2  = allow2 ? A[l] : NEG2;
                    const float m01 = fmaxf(a0, a1);
                    const float n01 = fminf(a0, a1);
                    const float m   = fmaxf(m01, a2);
                    const float s2  = fmaxf(n01, fminf(m01, a2));  // 2nd largest
                    const float s3  = fminf(n01, a2);              // 3rd largest
                    const __half2 he = h2ex2_(__floats2half2_rn(s2 - m, s3 - m));
                    const float2 ef = __half22float2(he);
                    v = m + lg2f_(1.0f + ef.x + ef.y) + g;
                }
                abuf[cur ^ 1][2 + l] = v;
                a_own = v;
            }
            __syncthreads();
            cur ^= 1;
        }
    }

    if (tid == 0) {
        const float* A = abuf[cur];
        const int idx = 2 * Lt;
        const float la2 = lse2_(A[2 + idx], A[1 + idx]);
        float loss = -la2 * LN2_F;
        if (!isfinite(loss) || loss > 0.5e30f) loss = 0.0f;   // zero_infinity
        g_partial[b] = loss / (float)Lt;
    }
}

// ---------------------------------------------------------------------------
// Phase 3: mean over batch -> out[0]
// ---------------------------------------------------------------------------
__global__ void ctc_phase3(float* __restrict__ out)
{
    const int lane = threadIdx.x;
    float v = g_partial[lane] + g_partial[lane + 32];
#pragma unroll
    for (int o = 16; o; o >>= 1) v += __shfl_xor_sync(0xffffffffu, v, o);
    if (lane == 0) out[0] = v / (float)B_DIM;
}

// ---------------------------------------------------------------------------
extern "C" void kernel_launch(void* const* d_in, const int* in_sizes, int n_in,
                              void* d_out, int out_size)
{
    const float* x    = (const float*)d_in[0];   // (T, B, V) float32
    const int*   tgt  = (const int*)d_in[1];     // (B, S) int32
    const int*   ilen = (const int*)d_in[2];     // (B,) int32
    const int*   tlen = (const int*)d_in[3];     // (B,) int32
    float*       out  = (float*)d_out;

    dim3 g1(B_DIM, T_DIM / 8);
    ctc_phase1<<<g1, 256>>>(x, tgt);
    ctc_phase2<<<B_DIM, NTH>>>(tgt, ilen, tlen);
    ctc_phase3<<<1, 32>>>(out);
}

// round 14
// speedup vs baseline: 2.9192x; 1.1295x over previous
#include <cuda_runtime.h>
#include <cuda_fp16.h>
#include <cstdint>
#include <math.h>

// Problem constants (CTCLoss_70961449664599): T=2048, B=64, V=512, S=256
#define T_DIM 2048
#define B_DIM 64
#define V_DIM 512
#define S_DIM 256
#define CHUNK 16                 // time steps staged per cp.async chunk
#define TPAD  (T_DIM + 2 * CHUNK)
#define NEG2  (-1.0e30f)
#define LOG2E_F 1.4426950408889634f
#define LN2_F   0.6931471805599453f

// Scratch (allocation-free rule: __device__ globals).
// G2[b][t][p] = half2( log2 p(symbol targets[b][p]), log2 p(blank) )
__device__ __align__(16) __half2 g_G2[(size_t)B_DIM * TPAD * S_DIM];
__device__ float g_partial[B_DIM];

__device__ __forceinline__ float ex2f_(float x) {
    float y; asm("ex2.approx.f32 %0, %1;" : "=f"(y) : "f"(x)); return y;
}
__device__ __forceinline__ float lg2f_(float x) {
    float y; asm("lg2.approx.f32 %0, %1;" : "=f"(y) : "f"(x)); return y;
}
__device__ __forceinline__ __half2 h2ex2_(__half2 x) {   // 1 MUFU, two exp2s
    unsigned int xi = *reinterpret_cast<unsigned int*>(&x), yi;
    asm("ex2.approx.f16x2 %0, %1;" : "=r"(yi) : "r"(xi));
    return *reinterpret_cast<__half2*>(&yi);
}
__device__ __forceinline__ float lse2_(float a, float b) {   // 2 MUFU
    const float m = fmaxf(a, b);
    return m + lg2f_(1.0f + ex2f_(-fabsf(a - b)));
}
// 3-term logaddexp2, 2 MUFU via f16x2 ex2 of the two non-max deltas
__device__ __forceinline__ float lse3f16_(float a0, float a1, float a2) {
    const float m01 = fmaxf(a0, a1);
    const float n01 = fminf(a0, a1);
    const float m   = fmaxf(m01, a2);
    const float s2  = fmaxf(n01, fminf(m01, a2));   // 2nd largest
    const float s3  = fminf(n01, a2);               // 3rd largest
    const __half2 he = h2ex2_(__floats2half2_rn(s2 - m, s3 - m));
    const float2 ef = __half22float2(he);
    return m + lg2f_(1.0f + ef.x + ef.y);
}
__device__ __forceinline__ unsigned int smem_u32(const void* p) {
    unsigned int a;
    asm("{ .reg .u64 t; cvta.to.shared.u64 t, %1; cvt.u32.u64 %0, t; }"
        : "=r"(a) : "l"(p));
    return a;
}

// ---------------------------------------------------------------------------
// Phase 1: log-softmax (log2 domain) + gather into half2 (symbol, blank).
// Grid: (B, T/8), block: 256 threads (8 warps, 1 warp per t-row)
// ---------------------------------------------------------------------------
__global__ __launch_bounds__(256) void ctc_phase1(
    const float* __restrict__ x, const int* __restrict__ targets)
{
    __shared__ float sh_row[8][V_DIM];
    __shared__ int   sh_tgt[S_DIM];

    const int b    = blockIdx.x;
    const int tid  = threadIdx.x;
    const int w    = tid >> 5;
    const int lane = tid & 31;

    sh_tgt[tid] = targets[b * S_DIM + tid];
    __syncthreads();

    const int t = blockIdx.y * 8 + w;
    const float4* row = (const float4*)(x + ((size_t)t * B_DIM + b) * V_DIM);

    float s = 0.0f;
    float4* shv = (float4*)sh_row[w];
#pragma unroll
    for (int k = 0; k < 4; k++) {
        float4 v = row[lane + 32 * k];
        shv[lane + 32 * k] = v;
        s += ex2f_(v.x * LOG2E_F) + ex2f_(v.y * LOG2E_F)
           + ex2f_(v.z * LOG2E_F) + ex2f_(v.w * LOG2E_F);
    }
#pragma unroll
    for (int o = 16; o; o >>= 1) s += __shfl_xor_sync(0xffffffffu, s, o);
    const float lse2v = lg2f_(s);
    const float blankv = sh_row[w][0] * LOG2E_F - lse2v;

    __half2* gout = g_G2 + ((size_t)b * TPAD + t) * S_DIM;
#pragma unroll
    for (int j = lane; j < 256; j += 32) {
        const float symv = sh_row[w][sh_tgt[j]] * LOG2E_F - lse2v;
        gout[j] = __floats2half2_rn(symv, blankv);   // .x = symbol, .y = blank
    }
}

// ---------------------------------------------------------------------------
// Phase 2: alpha recursion (log2 domain), folded pairs, 9 warps.
//   thread p < 256 : owns positions 2p (blank, reg a_e) and 2p+1 (sym, reg a_o)
//   thread 256     : owns position 512 (blank)
//   threads 257..287: idle
// Per step: 1 LDS of neighbor odd alpha + 1 LDS of G2 pair + lse2 + lse3 +
// 1 STS of own odd alpha + one __syncthreads. G staged via cp.async ring.
// ---------------------------------------------------------------------------
#define NTH 288
__global__ __launch_bounds__(NTH) void ctc_phase2(
    const int* __restrict__ targets,
    const int* __restrict__ in_len,
    const int* __restrict__ tgt_len)
{
    __shared__ __align__(16) __half2 sg[2][CHUNK * 256];  // 2 x 16 KB
    __shared__ float aodd[2][258];    // [x][0] = NEG2 pad; [x][1+q] = pair q odd
    __shared__ float sh_e[257];       // final even alphas for readout

    const int b   = blockIdx.x;
    const int tid = threadIdx.x;
    const int Lin = in_len[b];         // block-uniform
    const int Lt  = tgt_len[b];

    const bool mainp = (tid < 256);
    const bool t512  = (tid == 256);
    const bool act   = (tid <= 256);
    const int  p     = mainp ? tid : 255;   // G2 column (t512 reads col 255's blank)

    bool allow2 = false;
    if (mainp) {
        const int curt  = targets[b * S_DIM + p];
        const int prevt = (p > 0) ? targets[b * S_DIM + p - 1] : 0;
        allow2 = (curt != prevt);      // symbols >= 1, repeat check only
    }

    const __half2* gb2 = g_G2 + (size_t)b * TPAD * S_DIM;

    // t = 0 init: only positions 0 (blank), 1 (symbol 0) live
    float a_e = NEG2, a_o = NEG2;
    if (tid == 0) {
        const __half2 g0 = __ldg(gb2);
        a_e = __high2float(g0);
        a_o = __low2float(g0);
    }
    if (act) aodd[0][1 + tid] = mainp ? a_o : NEG2;   // [257] unused-safe
    if (tid < 2) { aodd[0][0] = NEG2; aodd[1][0] = NEG2; }

    const unsigned int sd0 = smem_u32(&sg[0][0]);
    const unsigned int sd1 = smem_u32(&sg[1][0]);

    // stage chunk c = G2 rows [1 + c*CHUNK, +CHUNK) -> sg[c&1]  (16 KB)
    auto stage = [&](int c) {
        const char* src = (const char*)(gb2 + (size_t)(1 + c * CHUNK) * 256);
        const unsigned int dst = (c & 1) ? sd1 : sd0;
#pragma unroll
        for (int k = 0; k < 4; k++) {          // 1024 uint4 total
            const int e = tid + k * NTH;
            if (e < CHUNK * 256 / 4) {
                asm volatile("cp.async.cg.shared.global [%0], [%1], 16;"
                             :: "r"(dst + e * 16), "l"(src + (size_t)e * 16));
            }
        }
        asm volatile("cp.async.commit_group;");
    };

    stage(0);
    const int nsteps = Lin - 1;
    const int nch = (nsteps + CHUNK - 1) / CHUNK;

    int cur = 0;
    for (int c = 0; c < nch; c++) {
        stage(c + 1);
        asm volatile("cp.async.wait_group 1;");
        __syncthreads();                       // chunk c + aodd state visible

        const __half2* sb = sg[c & 1];
        const int tmax = min(CHUNK, nsteps - c * CHUNK);   // block-uniform
        for (int k = 0; k < tmax; k++) {
            if (act) {
                const float a_left = aodd[cur][tid];        // old alpha(2p-1)
                const __half2 h = sb[k * 256 + p];
                if (mainp) {
                    const float gs  = __low2float(h);
                    const float gbl = __high2float(h);
                    const float ne = lse2_(a_e, a_left) + gbl;
                    const float no = lse3f16_(a_o, a_e, allow2 ? a_left : NEG2) + gs;
                    a_e = ne; a_o = no;
                    aodd[cur ^ 1][1 + tid] = no;
                } else {
                    a_e = lse2_(a_e, a_left) + __high2float(h);  // pos 512
                }
            }
            __syncthreads();
            cur ^= 1;
        }
    }

    if (act) sh_e[tid] = a_e;
    __syncthreads();

    if (tid == 0) {
        // alpha(2Lt) = even of pair Lt; alpha(2Lt-1) = odd of pair Lt-1
        const float ae = sh_e[Lt];
        const float ao = aodd[cur][Lt];        // index 1 + (Lt-1)
        const float la2 = lse2_(ae, ao);
        float loss = -la2 * LN2_F;
        if (!isfinite(loss) || loss > 0.5e30f) loss = 0.0f;   // zero_infinity
        g_partial[b] = loss / (float)Lt;
    }
}

// ---------------------------------------------------------------------------
// Phase 3: mean over batch -> out[0]
// ---------------------------------------------------------------------------
__global__ void ctc_phase3(float* __restrict__ out)
{
    const int lane = threadIdx.x;
    float v = g_partial[lane] + g_partial[lane + 32];
#pragma unroll
    for (int o = 16; o; o >>= 1) v += __shfl_xor_sync(0xffffffffu, v, o);
    if (lane == 0) out[0] = v / (float)B_DIM;
}

// ---------------------------------------------------------------------------
extern "C" void kernel_launch(void* const* d_in, const int* in_sizes, int n_in,
                              void* d_out, int out_size)
{
    const float* x    = (const float*)d_in[0];   // (T, B, V) float32
    const int*   tgt  = (const int*)d_in[1];     // (B, S) int32
    const int*   ilen = (const int*)d_in[2];     // (B,) int32
    const int*   tlen = (const int*)d_in[3];     // (B,) int32
    float*       out  = (float*)d_out;

    dim3 g1(B_DIM, T_DIM / 8);
    ctc_phase1<<<g1, 256>>>(x, tgt);
    ctc_phase2<<<B_DIM, NTH>>>(tgt, ilen, tlen);
    ctc_phase3<<<1, 32>>>(out);
}